// round 1
// baseline (speedup 1.0000x reference)
#include <cuda_runtime.h>

// AdditiveAttention (Bahdanau): B=2, L=S=512, H=8, E=32, D=64
// scores[b,h,l,s] = sum_e v_e * tanh(q[b,l,h,e] + k[b,s,h,e]) + mask[l,s] + klen[b,s]
// out[b,l,h,d]    = softmax_s(scores) @ values[b,s,h,d]
//
// tanh(x) = 1 - 2/(1+e^{2x}); with q,k pre-scaled by 2*log2(e):
//   score = (sum_e v_e) + sum_e (-2 v_e) * rcp(1 + ex2(qs_e + ks_e))
// -> inner loop: FADD, MUFU.EX2, FADD, MUFU.RCP, FFMA  (MUFU-bound kernel)

#define BB 2
#define LL 512
#define SS 512
#define HH 8
#define EE 32
#define DD 64
#define LT 16          // L-rows per CTA
#define NT 256         // threads per CTA
#define SPAD 513       // kT row pad (conflict-free)

__device__ __forceinline__ float ex2f(float x) {
    float y; asm("ex2.approx.f32 %0, %1;" : "=f"(y) : "f"(x)); return y;
}
__device__ __forceinline__ float rcpf(float x) {
    float y; asm("rcp.approx.f32 %0, %1;" : "=f"(y) : "f"(x)); return y;
}

struct Smem {
    float kT[EE * SPAD];      // pre-scaled keys, [e][s], padded rows
    float scores[LT * SS];    // scores -> unnormalized probs
    float klen[SS];           // key_lengths_add[b, :]
    float rowsum[LT];         // softmax denominators
    float part[2 * LT * DD];  // AV partials (two s-halves)
};

__global__ void __launch_bounds__(NT, 2)
addattn_kernel(const float* __restrict__ q, const float* __restrict__ k,
               const float* __restrict__ vals, const float* __restrict__ vvec,
               const float* __restrict__ amask, const float* __restrict__ klen_g,
               float* __restrict__ out)
{
    extern __shared__ unsigned char smem_raw[];
    Smem& sm = *reinterpret_cast<Smem*>(smem_raw);

    const int tid = threadIdx.x;
    const int bid = blockIdx.x;            // grid = B*H*(L/LT) = 2*8*32 = 512
    const int lt  = bid & 31;
    const int h   = (bid >> 5) & 7;
    const int b   = bid >> 8;
    const int l0  = lt * LT;

    const float SCALE = 2.8853900817779268f;   // 2*log2(e)
    const float L2E   = 1.4426950408889634f;   // log2(e)

    // ---- load keys -> smem transposed [e][s], pre-scaled ----
    const float* kbase = k + ((size_t)b * SS) * (HH * EE) + (size_t)h * EE;
    for (int i = tid; i < SS * EE; i += NT) {
        int s = i >> 5, e = i & 31;
        sm.kT[e * SPAD + s] = kbase[(size_t)s * (HH * EE) + e] * SCALE;
    }
    for (int s = tid; s < SS; s += NT)
        sm.klen[s] = klen_g[b * SS + s];

    // ---- per-thread row: q (pre-scaled) and -2*v in registers ----
    const int lr   = tid >> 4;     // 0..15 (L-row in tile)
    const int scol = tid & 15;     // s sub-column
    const float* qrow = q + (((size_t)(b * LL + l0 + lr)) * HH + h) * EE;
    float qs[EE], vm2[EE];
    float vsum = 0.f;
#pragma unroll
    for (int e = 0; e < EE; e++) {
        qs[e] = qrow[e] * SCALE;
        float ve = __ldg(&vvec[e]);
        vm2[e] = -2.f * ve;
        vsum += ve;
    }
    __syncthreads();

    // ---- phase 1: scores (MUFU-bound inner loop) ----
    const float* amrow = amask + (size_t)(l0 + lr) * SS;
    for (int j = 0; j < SS / 16; j++) {
        int s = scol + 16 * j;
        float acc = vsum;
#pragma unroll
        for (int e = 0; e < EE; e++) {
            float x = qs[e] + sm.kT[e * SPAD + s];
            float t = ex2f(x);
            float r = rcpf(t + 1.0f);
            acc = fmaf(vm2[e], r, acc);
        }
        sm.scores[lr * SS + s] = acc + sm.klen[s] + amrow[s];
    }
    __syncthreads();

    // ---- phase 2: row softmax (unnormalized probs + rowsum) ----
    const int wid = tid >> 5, lane = tid & 31;
    for (int r = wid; r < LT; r += 8) {
        float x[16];
        float m = -1e30f;
#pragma unroll
        for (int j = 0; j < 16; j++) {
            x[j] = sm.scores[r * SS + lane + 32 * j];
            m = fmaxf(m, x[j]);
        }
#pragma unroll
        for (int o = 16; o > 0; o >>= 1)
            m = fmaxf(m, __shfl_xor_sync(0xffffffffu, m, o));
        float sum = 0.f;
#pragma unroll
        for (int j = 0; j < 16; j++) {
            float p = ex2f((x[j] - m) * L2E);
            sm.scores[r * SS + lane + 32 * j] = p;
            sum += p;
        }
#pragma unroll
        for (int o = 16; o > 0; o >>= 1)
            sum += __shfl_xor_sync(0xffffffffu, sum, o);
        if (lane == 0) sm.rowsum[r] = sum;
    }
    __syncthreads();

    // ---- phase 3: A @ V, 4 rows/warp register-blocked, 2 s-halves ----
    const int rg = wid & 3;       // row group (4 rows)
    const int sh = wid >> 2;      // s-half
    const int d0 = lane * 2;
    const float* vbase = vals + ((size_t)(b * SS) * HH + h) * DD;
    float2 acc4[4];
#pragma unroll
    for (int i = 0; i < 4; i++) acc4[i] = make_float2(0.f, 0.f);

    const int sbeg = sh * 256;
#pragma unroll 4
    for (int s = sbeg; s < sbeg + 256; s++) {
        float2 vv = *reinterpret_cast<const float2*>(vbase + (size_t)s * (HH * DD) + d0);
#pragma unroll
        for (int i = 0; i < 4; i++) {
            float a = sm.scores[(rg * 4 + i) * SS + s];   // broadcast LDS
            acc4[i].x = fmaf(a, vv.x, acc4[i].x);
            acc4[i].y = fmaf(a, vv.y, acc4[i].y);
        }
    }
#pragma unroll
    for (int i = 0; i < 4; i++) {
        int row = rg * 4 + i;
        *reinterpret_cast<float2*>(&sm.part[(sh * LT + row) * DD + d0]) = acc4[i];
    }
    __syncthreads();

    // ---- combine halves, normalize, store ----
    for (int i = tid; i < LT * DD; i += NT) {
        int row = i >> 6, d = i & 63;
        float val = (sm.part[row * DD + d] + sm.part[(LT + row) * DD + d]) / sm.rowsum[row];
        out[(((size_t)(b * LL + l0 + row)) * HH + h) * DD + d] = val;
    }
}

extern "C" void kernel_launch(void* const* d_in, const int* in_sizes, int n_in,
                              void* d_out, int out_size)
{
    (void)in_sizes; (void)n_in; (void)out_size;
    cudaFuncSetAttribute(addattn_kernel,
                         cudaFuncAttributeMaxDynamicSharedMemorySize,
                         (int)sizeof(Smem));
    const float* q     = (const float*)d_in[0];
    const float* k     = (const float*)d_in[1];
    const float* vals  = (const float*)d_in[2];
    const float* vvec  = (const float*)d_in[3];
    const float* amask = (const float*)d_in[4];
    const float* klen  = (const float*)d_in[5];
    addattn_kernel<<<BB * HH * (LL / LT), NT, sizeof(Smem)>>>(
        q, k, vals, vvec, amask, klen, (float*)d_out);
}

// round 4
// speedup vs baseline: 1.2925x; 1.2925x over previous
#include <cuda_runtime.h>

// AdditiveAttention (Bahdanau): B=2, L=S=512, H=8, E=32, D=64
// score[b,h,l,s] = sum_e v_e*tanh(q+k) + mask[l,s] + klen[b,s];  out = softmax_s @ values
//
// tanh(x) = 1 - 2/(1+e^{2x});  e^{2(q+k)} = Eq*Ek with Eq=ex2(2q*log2e), Ek=ex2(2k*log2e)
// -> inner loop per element: LDS + FFMA(t=Eq*Ek+1) + MUFU.RCP + FFMA  (1 MUFU/elem)

#define BB 2
#define LL 512
#define SS 512
#define HH 8
#define EE 32
#define DD 64
#define LT 8           // L-rows per CTA (one warp per row)
#define NT 256
#define SPAD 516       // Ek smem row stride (float4-aligned, bank-rotating)
#define SCALE 2.8853900817779268f   /* 2*log2(e) */
#define L2E   1.4426950408889634f

__device__ __forceinline__ float ex2f(float x) {
    float y; asm("ex2.approx.f32 %0, %1;" : "=f"(y) : "f"(x)); return y;
}
__device__ __forceinline__ float rcpf(float x) {
    float y; asm("rcp.approx.f32 %0, %1;" : "=f"(y) : "f"(x)); return y;
}

// Scratch for factorized exponentials (1MB each)
__device__ float g_Ek[BB * HH * EE * SS];   // [b][h][e][s]
__device__ float g_Eq[BB * LL * HH * EE];   // same layout as q

__global__ void prep_ek(const float* __restrict__ k) {
    int i = blockIdx.x * blockDim.x + threadIdx.x;   // BB*HH*EE*SS = 262144
    int s = i & (SS - 1);
    int e = (i >> 9) & (EE - 1);
    int h = (i >> 14) & (HH - 1);
    int b = i >> 17;
    float kv = k[(((size_t)(b * SS + s)) * HH + h) * EE + e];
    g_Ek[i] = ex2f(kv * SCALE);
}

__global__ void prep_eq(const float* __restrict__ q) {
    int i = blockIdx.x * blockDim.x + threadIdx.x;   // 262144, layout identical to q
    g_Eq[i] = ex2f(q[i] * SCALE);
}

struct SmemT {
    union {
        float ek[16 * SPAD];                 // one e-half of Ek, [e][s] padded (33KB)
        struct {                             // overlaid after Ek is dead:
            float probs[LT * SS];            // 16KB
            float part[2 * LT * DD];         // 4KB
            float rowsum[LT];
        } p2;
    } u;
    float eqrow[LT * EE];                    // Eq for this CTA's 8 rows
    float vm2[EE];                           // -2*v_e
    float klen[SS];
};

__global__ void __launch_bounds__(NT, 4)
addattn_main(const float* __restrict__ vals, const float* __restrict__ vvec,
             const float* __restrict__ amask, const float* __restrict__ klen_g,
             float* __restrict__ out)
{
    __shared__ SmemT sm;

    const int tid  = threadIdx.x;
    const int wid  = tid >> 5;      // warp = L-row (0..7)
    const int lane = tid & 31;
    const int bid  = blockIdx.x;    // grid = 2*8*64 = 1024
    const int lt   = bid & 63;
    const int h    = (bid >> 6) & 7;
    const int b    = bid >> 9;
    const int l0   = lt * LT;

    // ---- stage Eq rows, vm2, klen, Ek half-0 ----
    {
        int r = tid >> 5, e = tid & 31;   // 256 threads = 8 rows x 32 e
        sm.eqrow[tid] = g_Eq[(((size_t)(b * LL + l0 + r)) * HH + h) * EE + e];
    }
    if (tid < EE) sm.vm2[tid] = -2.0f * vvec[tid];
    for (int s = tid; s < SS; s += NT) sm.klen[s] = klen_g[b * SS + s];

    const float* ekg = g_Ek + ((size_t)(b * HH + h) * EE) * SS;  // [e][s], contiguous
#pragma unroll
    for (int i = tid; i < (16 * SS) / 4; i += NT) {              // 2048 float4
        float4 v4 = reinterpret_cast<const float4*>(ekg)[i];
        int e = i >> 7, s4 = i & 127;
        *reinterpret_cast<float4*>(&sm.u.ek[e * SPAD + s4 * 4]) = v4;
    }
    __syncthreads();

    float vsum = 0.f;
#pragma unroll
    for (int e = 0; e < EE; e++) vsum += sm.vm2[e];
    vsum *= -0.5f;                                 // sum_e v_e

    // ---- phase 1: scores fully in registers (lane owns s = lane+32j) ----
    float x[16];
#pragma unroll
    for (int j = 0; j < 16; j++) x[j] = vsum;

    for (int e = 0; e < 16; e++) {                 // e-half 0
        float eq = sm.eqrow[wid * EE + e];
        float vm = sm.vm2[e];
        const float* row = &sm.u.ek[e * SPAD + lane];
#pragma unroll
        for (int j = 0; j < 16; j++) {
            float t = fmaf(eq, row[32 * j], 1.0f);
            x[j] = fmaf(vm, rcpf(t), x[j]);
        }
    }
    __syncthreads();
    // stage Ek half-1
#pragma unroll
    for (int i = tid; i < (16 * SS) / 4; i += NT) {
        float4 v4 = reinterpret_cast<const float4*>(ekg + 16 * SS)[i];
        int e = i >> 7, s4 = i & 127;
        *reinterpret_cast<float4*>(&sm.u.ek[e * SPAD + s4 * 4]) = v4;
    }
    __syncthreads();
    for (int e = 0; e < 16; e++) {                 // e-half 1
        float eq = sm.eqrow[wid * EE + 16 + e];
        float vm = sm.vm2[16 + e];
        const float* row = &sm.u.ek[e * SPAD + lane];
#pragma unroll
        for (int j = 0; j < 16; j++) {
            float t = fmaf(eq, row[32 * j], 1.0f);
            x[j] = fmaf(vm, rcpf(t), x[j]);
        }
    }

    // ---- masks ----
    const float* amrow = amask + (size_t)(l0 + wid) * SS;
#pragma unroll
    for (int j = 0; j < 16; j++) {
        int s = lane + 32 * j;
        x[j] += sm.klen[s] + amrow[s];
    }
    __syncthreads();   // all warps done reading sm.u.ek before probs overlay

    // ---- phase 2: in-warp softmax (unnormalized) ----
    float m = -1e30f;
#pragma unroll
    for (int j = 0; j < 16; j++) m = fmaxf(m, x[j]);
#pragma unroll
    for (int o = 16; o > 0; o >>= 1)
        m = fmaxf(m, __shfl_xor_sync(0xffffffffu, m, o));
    float ssum = 0.f;
#pragma unroll
    for (int j = 0; j < 16; j++) {
        float p = ex2f((x[j] - m) * L2E);
        ssum += p;
        sm.u.p2.probs[wid * SS + lane + 32 * j] = p;
    }
#pragma unroll
    for (int o = 16; o > 0; o >>= 1)
        ssum += __shfl_xor_sync(0xffffffffu, ssum, o);
    if (lane == 0) sm.u.p2.rowsum[wid] = ssum;
    __syncthreads();

    // ---- phase 3: A @ V (4 row-groups x 2 s-halves, 2 rows/warp) ----
    const int rg = wid & 3, sh = wid >> 2;
    const int r0 = rg * 2, r1 = r0 + 1;
    const int d0 = lane * 2;
    const float* vb = vals + ((size_t)(b * SS) * HH + h) * DD;
    float2 a0 = make_float2(0.f, 0.f), a1 = make_float2(0.f, 0.f);
    const int sbeg = sh * 256;
#pragma unroll 4
    for (int s = sbeg; s < sbeg + 256; s++) {
        float2 vv = *reinterpret_cast<const float2*>(vb + (size_t)s * (HH * DD) + d0);
        float p0 = sm.u.p2.probs[r0 * SS + s];
        float p1 = sm.u.p2.probs[r1 * SS + s];
        a0.x = fmaf(p0, vv.x, a0.x);  a0.y = fmaf(p0, vv.y, a0.y);
        a1.x = fmaf(p1, vv.x, a1.x);  a1.y = fmaf(p1, vv.y, a1.y);
    }
    *reinterpret_cast<float2*>(&sm.u.p2.part[(sh * LT + r0) * DD + d0]) = a0;
    *reinterpret_cast<float2*>(&sm.u.p2.part[(sh * LT + r1) * DD + d0]) = a1;
    __syncthreads();

    // ---- combine halves, normalize, store ----
    for (int i = tid; i < LT * DD; i += NT) {
        int row = i >> 6, d = i & 63;
        float val = (sm.u.p2.part[row * DD + d] + sm.u.p2.part[(LT + row) * DD + d])
                    * rcpf(sm.u.p2.rowsum[row]);
        out[(((size_t)(b * LL + l0 + row)) * HH + h) * DD + d] = val;
    }
}

extern "C" void kernel_launch(void* const* d_in, const int* in_sizes, int n_in,
                              void* d_out, int out_size)
{
    (void)in_sizes; (void)n_in; (void)out_size;
    const float* q     = (const float*)d_in[0];
    const float* k     = (const float*)d_in[1];
    const float* vals  = (const float*)d_in[2];
    const float* vvec  = (const float*)d_in[3];
    const float* amask = (const float*)d_in[4];
    const float* klen  = (const float*)d_in[5];

    prep_eq<<<(BB * LL * HH * EE) / 256, 256>>>(q);
    prep_ek<<<(BB * HH * EE * SS) / 256, 256>>>(k);
    addattn_main<<<BB * HH * (LL / LT), NT>>>(vals, vvec, amask, klen, (float*)d_out);
}